// round 12
// baseline (speedup 1.0000x reference)
#include <cuda_runtime.h>
#include <cuda_bf16.h>
#include <stdint.h>

typedef unsigned long long ull;

// Problem dims
#define BDIM 32
#define TDIM 512
#define IDIM 512
#define HDIM 1024

// ---------------- scratch (static device globals; no allocation) ----------------
__device__ float g_xs[(size_t)TDIM * 8 * IDIM * 4];   // x staged: [t][grp][k][4b]
__device__ float g_hp1[8][4][HDIM * 4];               // h1 ring: [grp][slot][k][4b]
__device__ float g_hp2[8][4][HDIM * 4];               // h2 ring

__device__ unsigned g_fh1[1024];                      // [grp][cb] layer-0 progress
__device__ unsigned g_fh2[1024];                      // layer-1 progress

// ---------------- f32x2 helpers ----------------
__device__ __forceinline__ void ffma2(ull& d, ull a, ull b) {
    asm("fma.rn.f32x2 %0, %1, %2, %0;" : "+l"(d) : "l"(a), "l"(b));
}
__device__ __forceinline__ void add2(ull& d, ull a) {
    asm("add.rn.f32x2 %0, %0, %1;" : "+l"(d) : "l"(a));
}
__device__ __forceinline__ ull splat2(float x) {
    ull r;
    asm("mov.b64 %0, {%1, %1};" : "=l"(r) : "f"(x));
    return r;
}
__device__ __forceinline__ float2 unpack2(ull v) {
    float lo, hi;
    asm("mov.b64 {%0, %1}, %2;" : "=f"(lo), "=f"(hi) : "l"(v));
    return make_float2(lo, hi);
}
__device__ __forceinline__ float4 ldcg_f4(const void* p) {
    float4 v;
    asm volatile("ld.global.cg.v4.f32 {%0,%1,%2,%3}, [%4];"
                 : "=f"(v.x), "=f"(v.y), "=f"(v.z), "=f"(v.w) : "l"(p));
    return v;
}

// ---------------- init flags (inside graph; replayed every run) ----------------
__global__ void init_flags() {
    int i = blockIdx.x * blockDim.x + threadIdx.x;
    if (i < 1024) {
        g_fh1[i] = 0;
        g_fh2[i] = 0;
    }
}

// ---------------- stage x[B,T,I] -> g_xs[t][grp][k][4b] ----------------
__global__ __launch_bounds__(256) void stage_x(const float* __restrict__ x) {
    int t = blockIdx.x;
    int tid = threadIdx.x;
    for (int idx = tid; idx < 8 * IDIM; idx += 256) {
        int sg = idx >> 9;
        int k  = idx & 511;
        const float* xb = x + (size_t)t * IDIM + k;
        float4 v;
        v.x = xb[(size_t)(sg * 4 + 0) * TDIM * IDIM];
        v.y = xb[(size_t)(sg * 4 + 1) * TDIM * IDIM];
        v.z = xb[(size_t)(sg * 4 + 2) * TDIM * IDIM];
        v.w = xb[(size_t)(sg * 4 + 3) * TDIM * IDIM];
        *(float4*)(g_xs + (((size_t)t * 8 + sg) << 11) + k * 4) = v;
    }
}

// ---------------- acc structure and helpers ----------------
struct Accs { ull v[16]; };   // [A0 b0..3 | A1 b0..3 | B0 b0..3 | B1 b0..3]

__device__ __forceinline__ void zero_accs(Accs& a) {
    #pragma unroll
    for (int i = 0; i < 16; i++) a.v[i] = 0ull;
}

__device__ __forceinline__ void acc_step(Accs& a, ulonglong2 w1, ulonglong2 w2,
                                         float4 h) {
    ull s0 = splat2(h.x), s1 = splat2(h.y);
    ull s2 = splat2(h.z), s3 = splat2(h.w);
    ffma2(a.v[0],  s0, w1.x); ffma2(a.v[4],  s0, w1.y);
    ffma2(a.v[8],  s0, w2.x); ffma2(a.v[12], s0, w2.y);
    ffma2(a.v[1],  s1, w1.x); ffma2(a.v[5],  s1, w1.y);
    ffma2(a.v[9],  s1, w2.x); ffma2(a.v[13], s1, w2.y);
    ffma2(a.v[2],  s2, w1.x); ffma2(a.v[6],  s2, w1.y);
    ffma2(a.v[10], s2, w2.x); ffma2(a.v[14], s2, w2.y);
    ffma2(a.v[3],  s3, w1.x); ffma2(a.v[7],  s3, w1.y);
    ffma2(a.v[11], s3, w2.x); ffma2(a.v[15], s3, w2.y);
}

// generic dot: k covered as lane + 32*(4c+j), CHUNKS chunks of 4
template<int CHUNKS>
__device__ __forceinline__ void dot_into(Accs& ac,
                                         const char* __restrict__ wA,
                                         const char* __restrict__ wB,
                                         const char* __restrict__ hbase) {
    float4 hbuf[2][4];
    #pragma unroll
    for (int j = 0; j < 4; j++)
        hbuf[0][j] = ldcg_f4(hbase + j * 512);
    #pragma unroll
    for (int c = 0; c < CHUNKS; c++) {
        if (c < CHUNKS - 1) {
            #pragma unroll
            for (int j = 0; j < 4; j++)
                hbuf[(c + 1) & 1][j] = ldcg_f4(hbase + ((c + 1) * 4 + j) * 512);
        }
        #pragma unroll
        for (int j = 0; j < 4; j++) {
            int koff = (c * 4 + j) * 1024;
            ulonglong2 w1 = *(const ulonglong2*)(wA + koff);
            ulonglong2 w2 = *(const ulonglong2*)(wB + koff);
            acc_step(ac, w1, w2, hbuf[c & 1][j]);
        }
    }
}

// butterfly reduction of 16 acc-pairs across 32 lanes -> 1 pair per lane
__device__ __forceinline__ ull reduce16(ull* a, int lane) {
    #pragma unroll
    for (int i = 0; i < 16; i++) {
        ull r = __shfl_xor_sync(0xffffffffu, a[i], 16);
        add2(a[i], r);
    }
    {
        int bit = lane & 1;
        #pragma unroll
        for (int i = 0; i < 8; i++) {
            ull snd = bit ? a[i] : a[i + 8];
            ull rcv = __shfl_xor_sync(0xffffffffu, snd, 1);
            a[i] = bit ? a[i + 8] : a[i];
            add2(a[i], rcv);
        }
    }
    {
        int bit = (lane >> 1) & 1;
        #pragma unroll
        for (int i = 0; i < 4; i++) {
            ull snd = bit ? a[i] : a[i + 4];
            ull rcv = __shfl_xor_sync(0xffffffffu, snd, 2);
            a[i] = bit ? a[i + 4] : a[i];
            add2(a[i], rcv);
        }
    }
    {
        int bit = (lane >> 2) & 1;
        #pragma unroll
        for (int i = 0; i < 2; i++) {
            ull snd = bit ? a[i] : a[i + 2];
            ull rcv = __shfl_xor_sync(0xffffffffu, snd, 4);
            a[i] = bit ? a[i + 2] : a[i];
            add2(a[i], rcv);
        }
    }
    {
        int bit = (lane >> 3) & 1;
        ull snd = bit ? a[0] : a[1];
        ull rcv = __shfl_xor_sync(0xffffffffu, snd, 8);
        a[0] = bit ? a[1] : a[0];
        add2(a[0], rcv);
    }
    return a[0];
}

__device__ __forceinline__ ull norm_reduce(const Accs& ac, int lane, int half) {
    ull a[16];
    if (half == 0) {
        #pragma unroll
        for (int i = 0; i < 16; i++) a[i] = ac.v[i];
    } else {
        #pragma unroll
        for (int i = 0; i < 8; i++) {
            a[i]     = ac.v[i + 8];
            a[i + 8] = ac.v[i];
        }
    }
    return reduce16(a, lane);
}

__device__ __forceinline__ void poll_all(const unsigned* __restrict__ fpp,
                                         unsigned tt, int lane) {
    for (;;) {
        unsigned f0, f1, f2, f3;
        asm volatile("ld.acquire.gpu.u32 %0, [%1];" : "=r"(f0) : "l"(fpp + lane));
        asm volatile("ld.acquire.gpu.u32 %0, [%1];" : "=r"(f1) : "l"(fpp + lane + 32));
        asm volatile("ld.acquire.gpu.u32 %0, [%1];" : "=r"(f2) : "l"(fpp + lane + 64));
        asm volatile("ld.acquire.gpu.u32 %0, [%1];" : "=r"(f3) : "l"(fpp + lane + 96));
        bool ok = (f0 >= tt) & (f1 >= tt) & (f2 >= tt) & (f3 >= tt);
        if (__all_sync(0xffffffffu, ok)) break;
    }
}

// ---------------- role-split fused kernel ----------------
// 128 CTAs x 512 threads (16 warps). CTA cb owns cols [8cb,8cb+8) of both
// layers. Warps 0-7: layer-0 chain for group wid (x-dot + Whh0-dot).
// Warps 8-15: layer-1 chain for group wid-8 (Wih1-dot + Whh1-dot, single
// accumulator, single reduce). The two layers' poll/load/reduce latencies
// overlap across warps. 4-slot rings; L0 backpressures on fh2 >= i-3.
#define FU_SMEM_BYTES ((3 * 8 * HDIM + 8 * IDIM) * 4)   // 112KB

__global__ __launch_bounds__(512, 1) void recur_fused(
    const float* __restrict__ xs,
    const float* __restrict__ Whh0,
    const float* __restrict__ Wih0,
    const float* __restrict__ Wih1,
    const float* __restrict__ Whh1,
    const float* __restrict__ bih0,
    const float* __restrict__ bhh0,
    const float* __restrict__ bih1,
    const float* __restrict__ bhh1,
    float* __restrict__ out)
{
    extern __shared__ __align__(16) float sm[];
    float* Wh0 = sm;                       // [k][8c], k<1024
    float* Wi1 = sm + 8 * HDIM;
    float* Wh1 = sm + 16 * HDIM;
    float* Wi0 = sm + 24 * HDIM;           // [k][8c], k<512

    int tid  = threadIdx.x;
    int cb   = blockIdx.x;
    int lane = tid & 31;
    int wid  = tid >> 5;
    int sg   = wid & 7;

    for (int idx = tid; idx < 8 * HDIM; idx += 512) {
        int c = idx >> 10;
        int k = idx & 1023;
        Wh0[k * 8 + c] = __ldg(Whh0 + (size_t)(cb * 8 + c) * HDIM + k);
        Wi1[k * 8 + c] = __ldg(Wih1 + (size_t)(cb * 8 + c) * HDIM + k);
        Wh1[k * 8 + c] = __ldg(Whh1 + (size_t)(cb * 8 + c) * HDIM + k);
    }
    for (int idx = tid; idx < 8 * IDIM; idx += 512) {
        int c = idx >> 9;
        int k = idx & 511;
        Wi0[k * 8 + c] = __ldg(Wih0 + (size_t)(cb * 8 + c) * IDIM + k);
    }
    __syncthreads();

    int half = (lane >> 2) & 1;
    int cp_r = 2 * (lane & 1) + ((lane >> 1) & 1);
    int b_r  = 2 * ((lane >> 2) & 1) + ((lane >> 3) & 1);
    int col0 = cb * 8 + 2 * cp_r;
    int gb   = sg * 4 + b_r;

    const unsigned* fpp1 = g_fh1 + sg * 128;
    const unsigned* fpp2 = g_fh2 + sg * 128;

    if (wid < 8) {
        // ================= layer-0 warp =================
        unsigned* myf1 = g_fh1 + sg * 128 + cb;
        float2 b0sum;
        b0sum.x = __ldg(bih0 + col0) + __ldg(bhh0 + col0);
        b0sum.y = __ldg(bih0 + col0 + 1) + __ldg(bhh0 + col0 + 1);

        const char* wi0A = (const char*)Wi0 + lane * 32 + half * 16;
        const char* wi0B = (const char*)Wi0 + lane * 32 + (1 - half) * 16;
        const char* wh0A = (const char*)Wh0 + lane * 32 + half * 16;
        const char* wh0B = (const char*)Wh0 + lane * 32 + (1 - half) * 16;

        #pragma unroll 1
        for (int i = 0; i < TDIM; i++) {
            Accs xa;
            zero_accs(xa);

            // x-dot (independent prework)
            const char* xb = (const char*)(xs + (((size_t)i * 8 + sg) << 11))
                             + lane * 16;
            dot_into<4>(xa, wi0A, wi0B, xb);

            if (i > 0) {
                poll_all(fpp1, (unsigned)i, lane);
                if (i > 3) poll_all(fpp2, (unsigned)(i - 3), lane);  // ring WAR
                const char* hb = (const char*)&g_hp1[sg][(i - 1) & 3][0]
                                 + lane * 16;
                dot_into<8>(xa, wh0A, wh0B, hb);
            }

            float2 u = unpack2(norm_reduce(xa, lane, half));
            float v0 = tanhf(b0sum.x + u.x);
            float v1 = tanhf(b0sum.y + u.y);
            if (lane < 16) {
                float* pb = &g_hp1[sg][i & 3][0];
                pb[(col0 + 0) * 4 + b_r] = v0;
                pb[(col0 + 1) * 4 + b_r] = v1;
            }
            __syncwarp();
            if (lane == 0) {
                asm volatile("st.release.gpu.u32 [%0], %1;"
                             :: "l"(myf1), "r"((unsigned)(i + 1)));
            }
        }
    } else {
        // ================= layer-1 warp =================
        unsigned* myf2 = g_fh2 + sg * 128 + cb;
        float2 b1sum;
        b1sum.x = __ldg(bih1 + col0) + __ldg(bhh1 + col0);
        b1sum.y = __ldg(bih1 + col0 + 1) + __ldg(bhh1 + col0 + 1);

        const char* wi1A = (const char*)Wi1 + lane * 32 + half * 16;
        const char* wi1B = (const char*)Wi1 + lane * 32 + (1 - half) * 16;
        const char* wh1A = (const char*)Wh1 + lane * 32 + half * 16;
        const char* wh1B = (const char*)Wh1 + lane * 32 + (1 - half) * 16;

        #pragma unroll 1
        for (int s = 0; s < TDIM; s++) {
            poll_all(fpp1, (unsigned)(s + 1), lane);     // h1(s) ready
            if (s > 0) poll_all(fpp2, (unsigned)s, lane); // h2(s-1) ready

            Accs za;
            zero_accs(za);

            const char* hb1 = (const char*)&g_hp1[sg][s & 3][0] + lane * 16;
            dot_into<8>(za, wi1A, wi1B, hb1);

            if (s > 0) {
                const char* hb2 = (const char*)&g_hp2[sg][(s - 1) & 3][0]
                                  + lane * 16;
                dot_into<8>(za, wh1A, wh1B, hb2);
            }

            float2 u = unpack2(norm_reduce(za, lane, half));
            float v0 = tanhf(b1sum.x + u.x);
            float v1 = tanhf(b1sum.y + u.y);

            if (lane < 16) {
                *(float2*)(out + ((size_t)gb * TDIM + s) * HDIM + col0)
                    = make_float2(v0, v1);
                float* pb = &g_hp2[sg][s & 3][0];
                pb[(col0 + 0) * 4 + b_r] = v0;
                pb[(col0 + 1) * 4 + b_r] = v1;
            }
            __syncwarp();
            if (lane == 0) {
                asm volatile("st.release.gpu.u32 [%0], %1;"
                             :: "l"(myf2), "r"((unsigned)(s + 1)));
            }
        }
    }
}

// ---------------- launch ----------------
extern "C" void kernel_launch(void* const* d_in, const int* in_sizes, int n_in,
                              void* d_out, int out_size)
{
    const float* x    = (const float*)d_in[0];
    const float* Wih0 = (const float*)d_in[1];
    const float* Whh0 = (const float*)d_in[2];
    const float* bih0 = (const float*)d_in[3];
    const float* bhh0 = (const float*)d_in[4];
    const float* Wih1 = (const float*)d_in[5];
    const float* Whh1 = (const float*)d_in[6];
    const float* bih1 = (const float*)d_in[7];
    const float* bhh1 = (const float*)d_in[8];
    float* out = (float*)d_out;

    float* xs;
    cudaGetSymbolAddress((void**)&xs, g_xs);

    cudaFuncSetAttribute(recur_fused, cudaFuncAttributeMaxDynamicSharedMemorySize,
                         FU_SMEM_BYTES);

    init_flags<<<4, 256>>>();
    stage_x<<<TDIM, 256>>>(x);
    recur_fused<<<128, 512, FU_SMEM_BYTES>>>(xs, Whh0, Wih0, Wih1, Whh1,
                                             bih0, bhh0, bih1, bhh1, out);
}